// round 1
// baseline (speedup 1.0000x reference)
#include <cuda_runtime.h>
#include <math.h>

#define BB 128
#define AA 8732
#define CC 21
#define MM 8

// ---------------- scratch (no allocations allowed) ----------------
__device__ unsigned char g_cls[BB * AA];   // matched class per anchor (0..20)
__device__ float         g_ce[BB * AA];    // ce for negatives, 0 at positives
__device__ int           g_npos[BB];
__device__ float         g_conf_pos;
__device__ float         g_conf_hard;
__device__ float         g_loc_sum;
__device__ int           g_npos_total;

__global__ void k_zero() {
    g_conf_pos = 0.f; g_conf_hard = 0.f; g_loc_sum = 0.f; g_npos_total = 0;
}

// ---------------- matching: one block per batch image ----------------
__global__ void k_match(const float* __restrict__ locs,
                        const float* __restrict__ boxes,
                        const int*   __restrict__ labels,
                        const float* __restrict__ anchors) {
    const int b   = blockIdx.x;
    const int tid = threadIdx.x;
    const int T   = blockDim.x;      // 256
    const int lane = tid & 31, wid = tid >> 5;

    __shared__ float         s_iou[AA];
    __shared__ unsigned char s_obj[AA];
    __shared__ float s_bx[MM][4];    // scaled xy boxes
    __shared__ float s_raw[MM][4];   // raw pixel xy boxes
    __shared__ float s_area[MM];
    __shared__ int   s_lab[MM];
    __shared__ float s_wv[8][MM];
    __shared__ int   s_wi[8][MM];
    __shared__ int   s_afo[MM];
    __shared__ float s_red[8];
    __shared__ int   s_redi[8];

    if (tid < MM) {
        int m = tid;
        float x1 = boxes[(b * MM + m) * 4 + 0];
        float y1 = boxes[(b * MM + m) * 4 + 1];
        float x2 = boxes[(b * MM + m) * 4 + 2];
        float y2 = boxes[(b * MM + m) * 4 + 3];
        s_raw[m][0] = x1; s_raw[m][1] = y1; s_raw[m][2] = x2; s_raw[m][3] = y2;
        float sx1 = x1 / 300.f, sy1 = y1 / 300.f, sx2 = x2 / 300.f, sy2 = y2 / 300.f;
        s_bx[m][0] = sx1; s_bx[m][1] = sy1; s_bx[m][2] = sx2; s_bx[m][3] = sy2;
        s_area[m] = (sx2 - sx1) * (sy2 - sy1);
        s_lab[m]  = labels[b * MM + m];
    }
    __syncthreads();

    // phase 1: IoU, per-anchor argmax over objects, per-object running argmax over anchors
    float bestv[MM]; int besti[MM];
#pragma unroll
    for (int m = 0; m < MM; m++) { bestv[m] = -1.f; besti[m] = 0; }

    for (int a = tid; a < AA; a += T) {
        float cx = anchors[a * 4 + 0], cy = anchors[a * 4 + 1];
        float w  = anchors[a * 4 + 2], h  = anchors[a * 4 + 3];
        float ax1 = cx - w * 0.5f, ay1 = cy - h * 0.5f;
        float ax2 = cx + w * 0.5f, ay2 = cy + h * 0.5f;
        float areaA = (ax2 - ax1) * (ay2 - ay1);
        float bmv = -1.f; int bmi = 0;
#pragma unroll
        for (int m = 0; m < MM; m++) {
            float lx = fmaxf(s_bx[m][0], ax1);
            float ly = fmaxf(s_bx[m][1], ay1);
            float rx = fminf(s_bx[m][2], ax2);
            float ry = fminf(s_bx[m][3], ay2);
            float iw = fmaxf(rx - lx, 0.f), ih = fmaxf(ry - ly, 0.f);
            float inter = iw * ih;
            float iou = inter / (s_area[m] + areaA - inter);
            if (iou > bmv) { bmv = iou; bmi = m; }          // first-index tie-break
            if (iou > bestv[m]) { bestv[m] = iou; besti[m] = a; }
        }
        s_iou[a] = bmv;
        s_obj[a] = (unsigned char)bmi;
    }

    // reduce per-object best anchor (argmax over A, first index on tie)
#pragma unroll
    for (int m = 0; m < MM; m++) {
        float v = bestv[m]; int i = besti[m];
        for (int off = 16; off; off >>= 1) {
            float ov = __shfl_down_sync(0xffffffffu, v, off);
            int   oi = __shfl_down_sync(0xffffffffu, i, off);
            if (ov > v || (ov == v && oi < i)) { v = ov; i = oi; }
        }
        if (lane == 0) { s_wv[wid][m] = v; s_wi[wid][m] = i; }
    }
    __syncthreads();
    if (tid < MM) {
        int m = tid;
        float v = s_wv[0][m]; int i = s_wi[0][m];
        for (int w2 = 1; w2 < T / 32; w2++) {
            float ov = s_wv[w2][m]; int oi = s_wi[w2][m];
            if (ov > v || (ov == v && oi < i)) { v = ov; i = oi; }
        }
        s_afo[m] = i;
    }
    __syncthreads();
    if (tid == 0) {   // sequential last-wins override (matches scatter semantics)
        for (int m = 0; m < MM; m++) {
            int a = s_afo[m];
            s_obj[a] = (unsigned char)m;
            s_iou[a] = 1.0f;
        }
    }
    __syncthreads();

    // phase 2: labels + fused positive L1 loc loss
    int npos = 0; float lsum = 0.f;
    const float4* locs4 = (const float4*)locs;
    for (int a = tid; a < AA; a += T) {
        float iou = s_iou[a];
        int   m   = s_obj[a];
        int   cls = (iou < 0.5f) ? 0 : s_lab[m];
        g_cls[b * AA + a] = (unsigned char)cls;
        if (cls != 0) {
            npos++;
            float cx = anchors[a * 4 + 0], cy = anchors[a * 4 + 1];
            float w  = anchors[a * 4 + 2], h  = anchors[a * 4 + 3];
            float t0 = (s_raw[m][0] - cx) / (w / 10.f);
            float t1 = (s_raw[m][1] - cy) / (h / 10.f);
            float t2 = logf(s_raw[m][2] / w) * 5.f;
            float t3 = logf(s_raw[m][3] / h) * 5.f;
            float4 p = locs4[b * AA + a];
            lsum += fabsf(p.x - t0) + fabsf(p.y - t1) + fabsf(p.z - t2) + fabsf(p.w - t3);
        }
    }
    for (int off = 16; off; off >>= 1) {
        npos += __shfl_xor_sync(0xffffffffu, npos, off);
        lsum += __shfl_xor_sync(0xffffffffu, lsum, off);
    }
    if (lane == 0) { s_red[wid] = lsum; s_redi[wid] = npos; }
    __syncthreads();
    if (tid == 0) {
        float L = 0.f; int N = 0;
        for (int w2 = 0; w2 < T / 32; w2++) { L += s_red[w2]; N += s_redi[w2]; }
        g_npos[b] = N;
        atomicAdd(&g_npos_total, N);
        atomicAdd(&g_loc_sum, L);
    }
}

// ---------------- cross-entropy: one warp per anchor-row ----------------
__global__ void k_ce(const float* __restrict__ scores) {
    const int gw   = (blockIdx.x * blockDim.x + threadIdx.x) >> 5;
    const int lane = threadIdx.x & 31;
    const int wid  = threadIdx.x >> 5;
    __shared__ float sacc[8];

    float acc = 0.f;
    if (gw < BB * AA) {
        int row = gw;
        float x = (lane < CC) ? scores[row * CC + lane] : -INFINITY;
        float mx = x;
        for (int off = 16; off; off >>= 1)
            mx = fmaxf(mx, __shfl_xor_sync(0xffffffffu, mx, off));
        float e = __expf(x - mx);
        if (lane >= CC) e = 0.f;
        float s = e;
        for (int off = 16; off; off >>= 1)
            s += __shfl_xor_sync(0xffffffffu, s, off);
        int cls = g_cls[row];
        float xc = __shfl_sync(0xffffffffu, x, cls);
        float ce = mx + __logf(s) - xc;
        if (lane == 0) {
            g_ce[row] = (cls != 0) ? 0.f : ce;
            if (cls != 0) acc = ce;
        }
    }
    if (lane == 0) sacc[wid] = acc;
    __syncthreads();
    if (threadIdx.x == 0) {
        float t = 0.f;
        for (int w2 = 0; w2 < (int)(blockDim.x >> 5); w2++) t += sacc[w2];
        if (t != 0.f) atomicAdd(&g_conf_pos, t);
    }
}

// ---------------- exact top-k sum per row via radix bit-descend ----------------
// values are all >= 0 so float bits are uint-monotone; sum of top-k is
// order-invariant => identical to sort-then-mask.
__global__ void k_select() {
    const int b   = blockIdx.x;
    const int tid = threadIdx.x;
    const int T   = blockDim.x;   // 512
    const int lane = tid & 31, wid = tid >> 5;

    __shared__ float        sv[AA];
    __shared__ int          s_cnt[16];
    __shared__ float        s_sum[16];
    __shared__ unsigned int s_take;

    for (int i = tid; i < AA; i += T) sv[i] = g_ce[b * AA + i];
    __syncthreads();

    int k = 3 * g_npos[b];
    if (k > AA) k = AA;

    unsigned int prefix = 0u;
    for (int bit = 30; bit >= 0; --bit) {   // sign bit always 0 (values >= 0)
        unsigned int trial = prefix | (1u << bit);
        int c = 0;
        for (int i = tid; i < AA; i += T)
            if (__float_as_uint(sv[i]) >= trial) c++;
        for (int off = 16; off; off >>= 1) c += __shfl_xor_sync(0xffffffffu, c, off);
        if (lane == 0) s_cnt[wid] = c;
        __syncthreads();
        if (tid == 0) {
            int tot = 0;
            for (int w2 = 0; w2 < T / 32; w2++) tot += s_cnt[w2];
            s_take = (tot >= k) ? 1u : 0u;
        }
        __syncthreads();
        if (s_take) prefix = trial;
        __syncthreads();
    }
    // prefix == bit pattern of the k-th largest value
    float kth = __uint_as_float(prefix);
    int cgt = 0; float sgt = 0.f;
    for (int i = tid; i < AA; i += T) {
        float v = sv[i];
        if (__float_as_uint(v) > prefix) { cgt++; sgt += v; }
    }
    for (int off = 16; off; off >>= 1) {
        cgt += __shfl_xor_sync(0xffffffffu, cgt, off);
        sgt += __shfl_xor_sync(0xffffffffu, sgt, off);
    }
    if (lane == 0) { s_cnt[wid] = cgt; s_sum[wid] = sgt; }
    __syncthreads();
    if (tid == 0) {
        int Cg = 0; float S = 0.f;
        for (int w2 = 0; w2 < T / 32; w2++) { Cg += s_cnt[w2]; S += s_sum[w2]; }
        S += (float)(k - Cg) * kth;
        atomicAdd(&g_conf_hard, S);
    }
}

__global__ void k_final(float* out) {
    float np = (float)g_npos_total;
    out[0] = (g_conf_hard + g_conf_pos) / np + g_loc_sum / (np * 4.f);
}

extern "C" void kernel_launch(void* const* d_in, const int* in_sizes, int n_in,
                              void* d_out, int out_size) {
    const float* locs    = (const float*)d_in[0];
    const float* scores  = (const float*)d_in[1];
    const float* boxes   = (const float*)d_in[2];
    const int*   labels  = (const int*)d_in[3];
    const float* anchors = (const float*)d_in[4];
    float* out = (float*)d_out;

    k_zero<<<1, 1>>>();
    k_match<<<BB, 256>>>(locs, boxes, labels, anchors);
    const int rows = BB * AA;
    const int rows_per_block = 8;   // 256 threads = 8 warps, warp per row
    const int grid = (rows + rows_per_block - 1) / rows_per_block;
    k_ce<<<grid, 256>>>(scores);
    k_select<<<BB, 512>>>();
    k_final<<<1, 1>>>(out);
}

// round 2
// speedup vs baseline: 2.8085x; 2.8085x over previous
#include <cuda_runtime.h>
#include <math.h>

#define BB 128
#define AA 8732
#define CC 21
#define MM 8
#define TT 512
#define NW (TT / 32)

// dynamic smem layout
#define OFF_CLS  34928                    // float s_val[8732] ends here
#define OFF_TILE 43664                    // uchar s_obj[8732] (padded) ends here
#define SMEM_TOTAL (OFF_TILE + TT * CC * 4)   // + float tile[512*21] = 86672 B

// per-image partials (fully overwritten every launch -> no zero kernel)
__device__ float g_pos[BB], g_hard[BB], g_loc[BB];
__device__ int   g_np[BB];

__global__ void __launch_bounds__(TT, 1) k_fused(
    const float* __restrict__ locs,
    const float* __restrict__ scores,
    const float* __restrict__ boxes,
    const int*   __restrict__ labels,
    const float* __restrict__ anchors)
{
    extern __shared__ char dsm[];
    float*         s_val = (float*)dsm;                          // iou -> ce
    unsigned char* s_obj = (unsigned char*)(dsm + OFF_CLS);      // obj -> cls
    float*         s_tile = (float*)(dsm + OFF_TILE);            // score staging

    __shared__ float s_bx[MM][4], s_raw[MM][4], s_area[MM];
    __shared__ int   s_lab[MM];
    __shared__ float s_wv[NW][MM];
    __shared__ int   s_wi[NW][MM];
    __shared__ int   s_afo[MM];
    __shared__ float s_redf[NW];
    __shared__ int   s_redi[NW];
    __shared__ int   s_cnt[2][NW];
    __shared__ int   s_npos;
    __shared__ float s_lsum, s_cpos;

    const int b = blockIdx.x, tid = threadIdx.x;
    const int lane = tid & 31, wid = tid >> 5;
    const float4* anc4 = (const float4*)anchors;

    // ---- setup: load gt boxes/labels ----
    if (tid < MM) {
        int m = tid;
        float x1 = boxes[(b * MM + m) * 4 + 0];
        float y1 = boxes[(b * MM + m) * 4 + 1];
        float x2 = boxes[(b * MM + m) * 4 + 2];
        float y2 = boxes[(b * MM + m) * 4 + 3];
        s_raw[m][0] = x1; s_raw[m][1] = y1; s_raw[m][2] = x2; s_raw[m][3] = y2;
        float sx1 = x1 / 300.f, sy1 = y1 / 300.f, sx2 = x2 / 300.f, sy2 = y2 / 300.f;
        s_bx[m][0] = sx1; s_bx[m][1] = sy1; s_bx[m][2] = sx2; s_bx[m][3] = sy2;
        s_area[m] = (sx2 - sx1) * (sy2 - sy1);
        s_lab[m]  = labels[b * MM + m];
    }
    __syncthreads();

    // ---- phase A: IoU matching ----
    float bestv[MM]; int besti[MM];
#pragma unroll
    for (int m = 0; m < MM; m++) { bestv[m] = -1.f; besti[m] = 0; }

    for (int a = tid; a < AA; a += TT) {
        float4 an = anc4[a];
        float ax1 = an.x - an.z * 0.5f, ay1 = an.y - an.w * 0.5f;
        float ax2 = an.x + an.z * 0.5f, ay2 = an.y + an.w * 0.5f;
        float areaA = (ax2 - ax1) * (ay2 - ay1);
        float bmv = -1.f; int bmi = 0;
#pragma unroll
        for (int m = 0; m < MM; m++) {
            float lx = fmaxf(s_bx[m][0], ax1);
            float ly = fmaxf(s_bx[m][1], ay1);
            float rx = fminf(s_bx[m][2], ax2);
            float ry = fminf(s_bx[m][3], ay2);
            float iw = fmaxf(rx - lx, 0.f), ih = fmaxf(ry - ly, 0.f);
            float inter = iw * ih;
            float iou = inter / (s_area[m] + areaA - inter);
            if (iou > bmv) { bmv = iou; bmi = m; }            // first-index tie-break
            if (iou > bestv[m]) { bestv[m] = iou; besti[m] = a; }
        }
        s_val[a] = bmv;
        s_obj[a] = (unsigned char)bmi;
    }

    // per-object argmax over anchors (first index on tie)
#pragma unroll
    for (int m = 0; m < MM; m++) {
        float v = bestv[m]; int i = besti[m];
        for (int off = 16; off; off >>= 1) {
            float ov = __shfl_down_sync(0xffffffffu, v, off);
            int   oi = __shfl_down_sync(0xffffffffu, i, off);
            if (ov > v || (ov == v && oi < i)) { v = ov; i = oi; }
        }
        if (lane == 0) { s_wv[wid][m] = v; s_wi[wid][m] = i; }
    }
    __syncthreads();
    if (tid < MM) {
        int m = tid;
        float v = s_wv[0][m]; int i = s_wi[0][m];
        for (int w2 = 1; w2 < NW; w2++) {
            float ov = s_wv[w2][m]; int oi = s_wi[w2][m];
            if (ov > v || (ov == v && oi < i)) { v = ov; i = oi; }
        }
        s_afo[m] = i;
    }
    __syncthreads();
    if (tid == 0) {       // sequential last-wins scatter override
        for (int m = 0; m < MM; m++) {
            int a = s_afo[m];
            s_obj[a] = (unsigned char)m;
            s_val[a] = 1.0f;
        }
    }
    __syncthreads();

    // ---- phase B: labels + positive L1 loc loss ----
    int npos = 0; float lsum = 0.f;
    const float4* locs4 = (const float4*)locs + (size_t)b * AA;
    for (int a = tid; a < AA; a += TT) {
        float iou = s_val[a];
        int   m   = s_obj[a];
        int   cls = (iou < 0.5f) ? 0 : s_lab[m];
        s_obj[a] = (unsigned char)cls;        // in-place obj -> cls
        if (cls != 0) {
            npos++;
            float4 an = anc4[a];
            float t0 = (s_raw[m][0] - an.x) / (an.z / 10.f);
            float t1 = (s_raw[m][1] - an.y) / (an.w / 10.f);
            float t2 = logf(s_raw[m][2] / an.z) * 5.f;
            float t3 = logf(s_raw[m][3] / an.w) * 5.f;
            float4 p = locs4[a];
            lsum += fabsf(p.x - t0) + fabsf(p.y - t1) + fabsf(p.z - t2) + fabsf(p.w - t3);
        }
    }
    for (int off = 16; off; off >>= 1) {
        npos += __shfl_xor_sync(0xffffffffu, npos, off);
        lsum += __shfl_xor_sync(0xffffffffu, lsum, off);
    }
    if (lane == 0) { s_redf[wid] = lsum; s_redi[wid] = npos; }
    __syncthreads();
    if (tid == 0) {
        float L = 0.f; int N = 0;
        for (int w2 = 0; w2 < NW; w2++) { L += s_redf[w2]; N += s_redi[w2]; }
        s_npos = N; s_lsum = L;
    }
    __syncthreads();

    // ---- phase C: cross-entropy, thread-per-row with smem-staged tiles ----
    float cpos = 0.f;
    const float4* sc4 = (const float4*)(scores + (size_t)b * AA * CC);
    for (int t0r = 0; t0r < AA; t0r += TT) {
        int rows = AA - t0r; if (rows > TT) rows = TT;
        int n4 = (rows * CC) >> 2;                 // rows*21 always %4==0 here
        const float4* src = sc4 + ((size_t)t0r * CC >> 2);
        float4 v[6];
#pragma unroll
        for (int j = 0; j < 6; j++) {              // batched loads -> MLP~6
            int i = tid + j * TT;
            if (i < n4) v[j] = src[i];
        }
#pragma unroll
        for (int j = 0; j < 6; j++) {
            int i = tid + j * TT;
            if (i < n4) ((float4*)s_tile)[i] = v[j];
        }
        __syncthreads();
        if (tid < rows) {
            int row = t0r + tid;
            const float* x = s_tile + tid * CC;    // stride 21: bank-conflict-free
            float mx = x[0];
#pragma unroll
            for (int c = 1; c < CC; c++) mx = fmaxf(mx, x[c]);
            float s = 0.f;
#pragma unroll
            for (int c = 0; c < CC; c++) s += __expf(x[c] - mx);
            int cls = s_obj[row];
            float ce = mx + __logf(s) - x[cls];
            if (cls != 0) { cpos += ce; s_val[row] = 0.f; }
            else          s_val[row] = ce;
        }
        __syncthreads();
    }
    for (int off = 16; off; off >>= 1)
        cpos += __shfl_xor_sync(0xffffffffu, cpos, off);
    if (lane == 0) s_redf[wid] = cpos;
    __syncthreads();
    if (tid == 0) {
        float P = 0.f;
        for (int w2 = 0; w2 < NW; w2++) P += s_redf[w2];
        s_cpos = P;
    }
    __syncthreads();

    // ---- phase D: exact-ish top-k sum via register-resident bit descend ----
    unsigned int rbits[18];
#pragma unroll
    for (int j = 0; j < 18; j++) {
        int a = tid + j * TT;
        rbits[j] = (a < AA) ? __float_as_uint(s_val[a]) : 0u;
    }
    int k = 3 * s_npos; if (k > AA) k = AA;

    unsigned int prefix = 0u;
    for (int bit = 30; bit >= 8; --bit) {     // stop at bit 8: rel err <= 2^-14
        unsigned int trial = prefix | (1u << bit);
        int c = 0;
#pragma unroll
        for (int j = 0; j < 18; j++) c += (rbits[j] >= trial);
        for (int off = 16; off; off >>= 1) c += __shfl_xor_sync(0xffffffffu, c, off);
        if (lane == 0) s_cnt[bit & 1][wid] = c;
        __syncthreads();
        int tot = 0;
#pragma unroll
        for (int w2 = 0; w2 < NW; w2++) tot += s_cnt[bit & 1][w2];
        if (tot >= k) prefix = trial;
    }
    float kth = __uint_as_float(prefix);
    int cgt = 0; float sgt = 0.f;
#pragma unroll
    for (int j = 0; j < 18; j++) {
        if (rbits[j] > prefix) { cgt++; sgt += __uint_as_float(rbits[j]); }
    }
    for (int off = 16; off; off >>= 1) {
        cgt += __shfl_xor_sync(0xffffffffu, cgt, off);
        sgt += __shfl_xor_sync(0xffffffffu, sgt, off);
    }
    __syncthreads();
    if (lane == 0) { s_redi[wid] = cgt; s_redf[wid] = sgt; }
    __syncthreads();

    // ---- phase E: per-image outputs (no atomics) ----
    if (tid == 0) {
        int Cg = 0; float S = 0.f;
        for (int w2 = 0; w2 < NW; w2++) { Cg += s_redi[w2]; S += s_redf[w2]; }
        S += (float)(k - Cg) * kth;
        g_hard[b] = S;
        g_pos[b]  = s_cpos;
        g_loc[b]  = s_lsum;
        g_np[b]   = s_npos;
    }
}

__global__ void k_final(float* out) {
    const int tid = threadIdx.x;      // 128 threads
    const int lane = tid & 31, wid = tid >> 5;
    __shared__ float sp[4], sh[4], sl[4];
    __shared__ int   sn[4];
    float p = g_pos[tid], h = g_hard[tid], l = g_loc[tid];
    int   n = g_np[tid];
    for (int off = 16; off; off >>= 1) {
        p += __shfl_xor_sync(0xffffffffu, p, off);
        h += __shfl_xor_sync(0xffffffffu, h, off);
        l += __shfl_xor_sync(0xffffffffu, l, off);
        n += __shfl_xor_sync(0xffffffffu, n, off);
    }
    if (lane == 0) { sp[wid] = p; sh[wid] = h; sl[wid] = l; sn[wid] = n; }
    __syncthreads();
    if (tid == 0) {
        float P = 0.f, H = 0.f, L = 0.f; int N = 0;
        for (int w = 0; w < 4; w++) { P += sp[w]; H += sh[w]; L += sl[w]; N += sn[w]; }
        float np = (float)N;
        out[0] = (H + P) / np + L / (np * 4.f);
    }
}

extern "C" void kernel_launch(void* const* d_in, const int* in_sizes, int n_in,
                              void* d_out, int out_size) {
    const float* locs    = (const float*)d_in[0];
    const float* scores  = (const float*)d_in[1];
    const float* boxes   = (const float*)d_in[2];
    const int*   labels  = (const int*)d_in[3];
    const float* anchors = (const float*)d_in[4];
    float* out = (float*)d_out;

    cudaFuncSetAttribute(k_fused, cudaFuncAttributeMaxDynamicSharedMemorySize, SMEM_TOTAL);
    k_fused<<<BB, TT, SMEM_TOTAL>>>(locs, scores, boxes, labels, anchors);
    k_final<<<1, 128>>>(out);
}

// round 4
// speedup vs baseline: 3.8772x; 1.3805x over previous
#include <cuda_runtime.h>
#include <math.h>

#define BB 128
#define AA 8732
#define CC 21
#define MM 8
#define TT 512
#define NW (TT / 32)

// dynamic smem layout
#define OFF_CLS  34928                        // float s_val[8732] ends here
#define OFF_TILE 43664                        // uchar s_obj[8732] padded ends here
#define SMEM_TOTAL (OFF_TILE + TT * CC * 4)   // + float tile[512*21] = 86672 B

// per-image partials (fully overwritten every launch) + self-resetting ticket
__device__ float g_pos[BB], g_hard[BB], g_loc[BB];
__device__ int   g_np[BB];
__device__ int   g_ctr = 0;

__global__ void __launch_bounds__(TT, 1) k_fused(
    const float* __restrict__ locs,
    const float* __restrict__ scores,
    const float* __restrict__ boxes,
    const int*   __restrict__ labels,
    const float* __restrict__ anchors,
    float* __restrict__ out)
{
    extern __shared__ char dsm[];
    float*         s_val  = (float*)dsm;                         // iou -> ce
    unsigned char* s_obj  = (unsigned char*)(dsm + OFF_CLS);     // obj -> cls
    float*         s_tile = (float*)(dsm + OFF_TILE);            // score staging

    __shared__ float s_bx[MM][4], s_raw[MM][4], s_area[MM];
    __shared__ int   s_lab[MM];
    __shared__ float s_wv[NW][MM];
    __shared__ int   s_wi[NW][MM];
    __shared__ int   s_afo[MM];
    __shared__ float s_redf[NW];
    __shared__ int   s_redi[NW];
    __shared__ int   s_cnt[2][NW];
    __shared__ int   s_npos;
    __shared__ float s_lsum, s_cpos;

    const int b = blockIdx.x, tid = threadIdx.x;
    const int lane = tid & 31, wid = tid >> 5;
    const float4* anc4 = (const float4*)anchors;

    // ---- setup ----
    if (tid < MM) {
        int m = tid;
        float x1 = boxes[(b * MM + m) * 4 + 0];
        float y1 = boxes[(b * MM + m) * 4 + 1];
        float x2 = boxes[(b * MM + m) * 4 + 2];
        float y2 = boxes[(b * MM + m) * 4 + 3];
        s_raw[m][0] = x1; s_raw[m][1] = y1; s_raw[m][2] = x2; s_raw[m][3] = y2;
        float sx1 = x1 / 300.f, sy1 = y1 / 300.f, sx2 = x2 / 300.f, sy2 = y2 / 300.f;
        s_bx[m][0] = sx1; s_bx[m][1] = sy1; s_bx[m][2] = sx2; s_bx[m][3] = sy2;
        s_area[m] = (sx2 - sx1) * (sy2 - sy1);
        s_lab[m]  = labels[b * MM + m];
    }
    __syncthreads();

    // ---- phase A: IoU matching (fast division) ----
    {
        float bestv[MM]; int besti[MM];
#pragma unroll
        for (int m = 0; m < MM; m++) { bestv[m] = -1.f; besti[m] = 0; }

        for (int a = tid; a < AA; a += TT) {
            float4 an = anc4[a];
            float ax1 = an.x - an.z * 0.5f, ay1 = an.y - an.w * 0.5f;
            float ax2 = an.x + an.z * 0.5f, ay2 = an.y + an.w * 0.5f;
            float areaA = (ax2 - ax1) * (ay2 - ay1);
            float bmv = -1.f; int bmi = 0;
#pragma unroll
            for (int m = 0; m < MM; m++) {
                float lx = fmaxf(s_bx[m][0], ax1);
                float ly = fmaxf(s_bx[m][1], ay1);
                float rx = fminf(s_bx[m][2], ax2);
                float ry = fminf(s_bx[m][3], ay2);
                float iw = fmaxf(rx - lx, 0.f), ih = fmaxf(ry - ly, 0.f);
                float inter = iw * ih;
                float iou = __fdividef(inter, s_area[m] + areaA - inter);
                if (iou > bmv) { bmv = iou; bmi = m; }        // first-index tie-break
                if (iou > bestv[m]) { bestv[m] = iou; besti[m] = a; }
            }
            s_val[a] = bmv;
            s_obj[a] = (unsigned char)bmi;
        }

        // per-object argmax over anchors (first index on tie)
#pragma unroll
        for (int m = 0; m < MM; m++) {
            float v = bestv[m]; int i = besti[m];
            for (int off = 16; off; off >>= 1) {
                float ov = __shfl_down_sync(0xffffffffu, v, off);
                int   oi = __shfl_down_sync(0xffffffffu, i, off);
                if (ov > v || (ov == v && oi < i)) { v = ov; i = oi; }
            }
            if (lane == 0) { s_wv[wid][m] = v; s_wi[wid][m] = i; }
        }
        __syncthreads();
        if (tid < MM) {
            int m = tid;
            float v = s_wv[0][m]; int i = s_wi[0][m];
            for (int w2 = 1; w2 < NW; w2++) {
                float ov = s_wv[w2][m]; int oi = s_wi[w2][m];
                if (ov > v || (ov == v && oi < i)) { v = ov; i = oi; }
            }
            s_afo[m] = i;
        }
        __syncthreads();
        if (tid == 0) {       // sequential last-wins scatter override
            for (int m = 0; m < MM; m++) {
                int a = s_afo[m];
                s_obj[a] = (unsigned char)m;
                s_val[a] = 1.0f;
            }
        }
        __syncthreads();
    }

    // ---- phase B: labels + positive L1 loc loss ----
    {
        int npos = 0; float lsum = 0.f;
        const float4* locs4 = (const float4*)locs + (size_t)b * AA;
        for (int a = tid; a < AA; a += TT) {
            float iou = s_val[a];
            int   m   = s_obj[a];
            int   cls = (iou < 0.5f) ? 0 : s_lab[m];
            s_obj[a] = (unsigned char)cls;    // in-place obj -> cls
            if (cls != 0) {
                npos++;
                float4 an = anc4[a];
                float t0 = (s_raw[m][0] - an.x) * __fdividef(10.f, an.z);
                float t1 = (s_raw[m][1] - an.y) * __fdividef(10.f, an.w);
                float t2 = __logf(__fdividef(s_raw[m][2], an.z)) * 5.f;
                float t3 = __logf(__fdividef(s_raw[m][3], an.w)) * 5.f;
                float4 p = locs4[a];
                lsum += fabsf(p.x - t0) + fabsf(p.y - t1) + fabsf(p.z - t2) + fabsf(p.w - t3);
            }
        }
        for (int off = 16; off; off >>= 1) {
            npos += __shfl_xor_sync(0xffffffffu, npos, off);
            lsum += __shfl_xor_sync(0xffffffffu, lsum, off);
        }
        if (lane == 0) { s_redf[wid] = lsum; s_redi[wid] = npos; }
        __syncthreads();
        if (tid == 0) {
            float L = 0.f; int N = 0;
            for (int w2 = 0; w2 < NW; w2++) { L += s_redf[w2]; N += s_redi[w2]; }
            s_npos = N; s_lsum = L;
        }
        __syncthreads();
    }

    // ---- phase C: CE, thread-per-row, software-pipelined tiles ----
    {
        float cpos = 0.f;
        const float4* sc4 = (const float4*)(scores + (size_t)b * AA * CC);
        float4 v[6];
        // preload tile 0
        {
            int rows0 = AA < TT ? AA : TT;
            int n4 = (rows0 * CC) >> 2;
#pragma unroll
            for (int j = 0; j < 6; j++) {
                int i = tid + j * TT;
                if (i < n4) v[j] = sc4[i];
            }
        }
        for (int t0r = 0; t0r < AA; t0r += TT) {
            int rows = AA - t0r; if (rows > TT) rows = TT;
            int n4 = (rows * CC) >> 2;
#pragma unroll
            for (int j = 0; j < 6; j++) {
                int i = tid + j * TT;
                if (i < n4) ((float4*)s_tile)[i] = v[j];
            }
            __syncthreads();
            // issue next tile's loads; in flight during compute below
            int t1r = t0r + TT;
            if (t1r < AA) {
                int rows1 = AA - t1r; if (rows1 > TT) rows1 = TT;
                int n41 = (rows1 * CC) >> 2;
                const float4* src = sc4 + ((size_t)t1r * CC >> 2);
#pragma unroll
                for (int j = 0; j < 6; j++) {
                    int i = tid + j * TT;
                    if (i < n41) v[j] = src[i];
                }
            }
            if (tid < rows) {
                int row = t0r + tid;
                const float* x = s_tile + tid * CC;   // stride 21: conflict-free
                float mx = x[0];
#pragma unroll
                for (int c = 1; c < CC; c++) mx = fmaxf(mx, x[c]);
                float s = 0.f;
#pragma unroll
                for (int c = 0; c < CC; c++) s += __expf(x[c] - mx);
                int cls = s_obj[row];
                float ce = mx + __logf(s) - x[cls];
                if (cls != 0) { cpos += ce; s_val[row] = 0.f; }
                else          s_val[row] = ce;
            }
            __syncthreads();
        }
        for (int off = 16; off; off >>= 1)
            cpos += __shfl_xor_sync(0xffffffffu, cpos, off);
        if (lane == 0) s_redf[wid] = cpos;
        __syncthreads();
        if (tid == 0) {
            float P = 0.f;
            for (int w2 = 0; w2 < NW; w2++) P += s_redf[w2];
            s_cpos = P;
        }
        __syncthreads();
    }

    // ---- phase D: top-k sum via bit descend over smem values ----
    {
        int k = 3 * s_npos; if (k > AA) k = AA;

        unsigned int prefix = 0u;
        for (int bit = 30; bit >= 8; --bit) {   // stop at bit 8: rel err <= 2^-14
            unsigned int trial = prefix | (1u << bit);
            int c = 0;
            for (int i = tid; i < AA; i += TT)
                c += (__float_as_uint(s_val[i]) >= trial);
            for (int off = 16; off; off >>= 1) c += __shfl_xor_sync(0xffffffffu, c, off);
            if (lane == 0) s_cnt[bit & 1][wid] = c;
            __syncthreads();
            int tot = 0;
#pragma unroll
            for (int w2 = 0; w2 < NW; w2++) tot += s_cnt[bit & 1][w2];
            if (tot >= k) prefix = trial;
        }
        float kth = __uint_as_float(prefix);
        int cgt = 0; float sgt = 0.f;
        for (int i = tid; i < AA; i += TT) {
            float v = s_val[i];
            if (__float_as_uint(v) > prefix) { cgt++; sgt += v; }
        }
        for (int off = 16; off; off >>= 1) {
            cgt += __shfl_xor_sync(0xffffffffu, cgt, off);
            sgt += __shfl_xor_sync(0xffffffffu, sgt, off);
        }
        __syncthreads();
        if (lane == 0) { s_redi[wid] = cgt; s_redf[wid] = sgt; }
        __syncthreads();

        if (tid == 0) {
            int Cg = 0; float S = 0.f;
            for (int w2 = 0; w2 < NW; w2++) { Cg += s_redi[w2]; S += s_redf[w2]; }
            S += (float)(k - Cg) * kth;
            g_hard[b] = S;
            g_pos[b]  = s_cpos;
            g_loc[b]  = s_lsum;
            g_np[b]   = s_npos;
        }
    }

    // ---- phase E: last CTA reduces all per-image partials ----
    __threadfence();
    __shared__ int s_ticket;
    if (tid == 0) s_ticket = atomicAdd(&g_ctr, 1);
    __syncthreads();
    if (s_ticket == BB - 1) {
        __threadfence();
        __shared__ float sp[4], sh[4], sl[4];
        __shared__ int   sn[4];
        if (tid == 0) g_ctr = 0;           // self-reset for next graph replay
        if (tid < BB) {
            float p = g_pos[tid], h = g_hard[tid], l = g_loc[tid];
            int   n = g_np[tid];
            for (int off = 16; off; off >>= 1) {
                p += __shfl_xor_sync(0xffffffffu, p, off);
                h += __shfl_xor_sync(0xffffffffu, h, off);
                l += __shfl_xor_sync(0xffffffffu, l, off);
                n += __shfl_xor_sync(0xffffffffu, n, off);
            }
            if (lane == 0) { sp[wid] = p; sh[wid] = h; sl[wid] = l; sn[wid] = n; }
        }
        __syncthreads();
        if (tid == 0) {
            float P = 0.f, H = 0.f, L = 0.f; int N = 0;
            for (int w = 0; w < 4; w++) { P += sp[w]; H += sh[w]; L += sl[w]; N += sn[w]; }
            float np = (float)N;
            out[0] = (H + P) / np + L / (np * 4.f);
        }
    }
}

extern "C" void kernel_launch(void* const* d_in, const int* in_sizes, int n_in,
                              void* d_out, int out_size) {
    const float* locs    = (const float*)d_in[0];
    const float* scores  = (const float*)d_in[1];
    const float* boxes   = (const float*)d_in[2];
    const int*   labels  = (const int*)d_in[3];
    const float* anchors = (const float*)d_in[4];
    float* out = (float*)d_out;

    cudaFuncSetAttribute(k_fused, cudaFuncAttributeMaxDynamicSharedMemorySize, SMEM_TOTAL);
    k_fused<<<BB, TT, SMEM_TOTAL>>>(locs, scores, boxes, labels, anchors, out);
}

// round 6
// speedup vs baseline: 4.8124x; 1.2412x over previous
#include <cuda_runtime.h>
#include <stdint.h>
#include <math.h>

#define BB 128
#define AA 8732
#define CC 21
#define MM 8
#define TT 512
#define NW (TT / 32)
#define NT ((AA + TT - 1) / TT)          // 18 tiles
#define TILE_F4 (TT * CC / 4)            // 2688 float4 per full tile

// dynamic smem layout
#define OFF_VAL  0
#define OFF_CLS  34928                   // float s_val[8732]
#define OFF_BUF0 43664                   // uchar s_obj padded to 8736
#define OFF_BUF1 (OFF_BUF0 + TT * CC * 4)
#define SMEM_TOTAL (OFF_BUF1 + TT * CC * 4)   // 129680 B

// per-image partials (fully overwritten every launch) + self-resetting ticket
__device__ float g_pos[BB], g_hard[BB], g_loc[BB];
__device__ int   g_np[BB];
__device__ int   g_ctr = 0;

__device__ __forceinline__ void cp16_pred(unsigned int dst, const void* src, int ok) {
    asm volatile("{\n\t.reg .pred p;\n\tsetp.ne.s32 p, %2, 0;\n\t"
                 "@p cp.async.cg.shared.global [%0], [%1], 16;\n\t}"
                 :: "r"(dst), "l"(src), "r"(ok));
}
#define CP_COMMIT() asm volatile("cp.async.commit_group;" ::: "memory")
#define CP_WAIT1()  asm volatile("cp.async.wait_group 1;" ::: "memory")

__global__ void __launch_bounds__(TT, 1) k_fused(
    const float* __restrict__ locs,
    const float* __restrict__ scores,
    const float* __restrict__ boxes,
    const int*   __restrict__ labels,
    const float* __restrict__ anchors,
    float* __restrict__ out)
{
    extern __shared__ char dsm[];
    float*         s_val = (float*)dsm;                       // iou -> ce
    unsigned char* s_obj = (unsigned char*)(dsm + OFF_CLS);   // obj -> cls

    __shared__ float s_bx[MM][4], s_raw[MM][4], s_area[MM];
    __shared__ int   s_lab[MM];
    __shared__ float s_wv[NW][MM];
    __shared__ int   s_wi[NW][MM];
    __shared__ int   s_afo[MM];
    __shared__ float s_redf[NW];
    __shared__ int   s_redi[NW];
    __shared__ unsigned s_cnt[2][NW];
    __shared__ int   s_npos;
    __shared__ float s_lsum, s_cpos;
    __shared__ int   s_bin1;  __shared__ unsigned s_chi;
    __shared__ unsigned s_prefix;
    __shared__ int   s_ticket;

    const int b = blockIdx.x, tid = threadIdx.x;
    const int lane = tid & 31, wid = tid >> 5;
    const float4* anc4 = (const float4*)anchors;
    const float4* sc4  = (const float4*)(scores + (size_t)b * AA * CC);

    // ---- prefetch tiles 0 & 1 via cp.async (land during phase A) ----
    {
#pragma unroll
        for (int t = 0; t < 2; t++) {
            int rows = AA - t * TT; if (rows > TT) rows = TT;
            int n4 = (rows * CC) >> 2;
            const float4* src = sc4 + (size_t)t * TILE_F4;
            unsigned int dbase = (unsigned int)__cvta_generic_to_shared(
                dsm + (t ? OFF_BUF1 : OFF_BUF0));
#pragma unroll
            for (int j = 0; j < 6; j++) {
                int i = tid + j * TT;
                int ok = i < n4;
                cp16_pred(ok ? (dbase + i * 16) : dbase,
                          ok ? (const void*)(src + i) : (const void*)sc4, ok);
            }
            CP_COMMIT();
        }
    }

    // ---- setup ----
    if (tid < MM) {
        int m = tid;
        float x1 = boxes[(b * MM + m) * 4 + 0];
        float y1 = boxes[(b * MM + m) * 4 + 1];
        float x2 = boxes[(b * MM + m) * 4 + 2];
        float y2 = boxes[(b * MM + m) * 4 + 3];
        s_raw[m][0] = x1; s_raw[m][1] = y1; s_raw[m][2] = x2; s_raw[m][3] = y2;
        float sx1 = x1 / 300.f, sy1 = y1 / 300.f, sx2 = x2 / 300.f, sy2 = y2 / 300.f;
        s_bx[m][0] = sx1; s_bx[m][1] = sy1; s_bx[m][2] = sx2; s_bx[m][3] = sy2;
        s_area[m] = (sx2 - sx1) * (sy2 - sy1);
        s_lab[m]  = labels[b * MM + m];
    }
    __syncthreads();

    // ---- phase A: IoU matching ----
    {
        float bestv[MM]; int besti[MM];
#pragma unroll
        for (int m = 0; m < MM; m++) { bestv[m] = -1.f; besti[m] = 0; }

        for (int a = tid; a < AA; a += TT) {
            float4 an = anc4[a];
            float ax1 = fmaf(an.z, -0.5f, an.x), ay1 = fmaf(an.w, -0.5f, an.y);
            float ax2 = fmaf(an.z,  0.5f, an.x), ay2 = fmaf(an.w,  0.5f, an.y);
            float areaA = (ax2 - ax1) * (ay2 - ay1);
            float bmv = -1.f; int bmi = 0;
#pragma unroll
            for (int m = 0; m < MM; m++) {
                float lx = fmaxf(s_bx[m][0], ax1);
                float ly = fmaxf(s_bx[m][1], ay1);
                float rx = fminf(s_bx[m][2], ax2);
                float ry = fminf(s_bx[m][3], ay2);
                float iw = fmaxf(rx - lx, 0.f), ih = fmaxf(ry - ly, 0.f);
                float inter = iw * ih;
                float iou = __fdividef(inter, s_area[m] + areaA - inter);
                if (iou > bmv) { bmv = iou; bmi = m; }        // first-index tie-break
                if (iou > bestv[m]) { bestv[m] = iou; besti[m] = a; }
            }
            s_val[a] = bmv;
            s_obj[a] = (unsigned char)bmi;
        }

#pragma unroll
        for (int m = 0; m < MM; m++) {
            float v = bestv[m]; int i = besti[m];
            for (int off = 16; off; off >>= 1) {
                float ov = __shfl_down_sync(0xffffffffu, v, off);
                int   oi = __shfl_down_sync(0xffffffffu, i, off);
                if (ov > v || (ov == v && oi < i)) { v = ov; i = oi; }
            }
            if (lane == 0) { s_wv[wid][m] = v; s_wi[wid][m] = i; }
        }
        __syncthreads();
        if (tid < MM) {
            int m = tid;
            float v = s_wv[0][m]; int i = s_wi[0][m];
            for (int w2 = 1; w2 < NW; w2++) {
                float ov = s_wv[w2][m]; int oi = s_wi[w2][m];
                if (ov > v || (ov == v && oi < i)) { v = ov; i = oi; }
            }
            s_afo[m] = i;
        }
        __syncthreads();
        if (tid == 0) {       // sequential last-wins scatter override
            for (int m = 0; m < MM; m++) {
                int a = s_afo[m];
                s_obj[a] = (unsigned char)m;
                s_val[a] = 1.0f;
            }
        }
        __syncthreads();
    }

    // ---- phase B: labels + positive L1 loc loss ----
    {
        int npos = 0; float lsum = 0.f;
        const float4* locs4 = (const float4*)locs + (size_t)b * AA;
        for (int a = tid; a < AA; a += TT) {
            float iou = s_val[a];
            int   m   = s_obj[a];
            int   cls = (iou < 0.5f) ? 0 : s_lab[m];
            s_obj[a] = (unsigned char)cls;    // in-place obj -> cls
            if (cls != 0) {
                npos++;
                float4 an = anc4[a];
                float t0 = (s_raw[m][0] - an.x) * __fdividef(10.f, an.z);
                float t1 = (s_raw[m][1] - an.y) * __fdividef(10.f, an.w);
                float t2 = __logf(__fdividef(s_raw[m][2], an.z)) * 5.f;
                float t3 = __logf(__fdividef(s_raw[m][3], an.w)) * 5.f;
                float4 p = locs4[a];
                lsum += fabsf(p.x - t0) + fabsf(p.y - t1) + fabsf(p.z - t2) + fabsf(p.w - t3);
            }
        }
        for (int off = 16; off; off >>= 1) {
            npos += __shfl_xor_sync(0xffffffffu, npos, off);
            lsum += __shfl_xor_sync(0xffffffffu, lsum, off);
        }
        if (lane == 0) { s_redf[wid] = lsum; s_redi[wid] = npos; }
        __syncthreads();
        if (tid == 0) {
            float L = 0.f; int N = 0;
            for (int w2 = 0; w2 < NW; w2++) { L += s_redf[w2]; N += s_redi[w2]; }
            s_npos = N; s_lsum = L;
        }
        __syncthreads();
    }

    // ---- phase C: CE, double-buffered cp.async pipeline ----
    {
        float cpos = 0.f;
        for (int t = 0; t < NT; t++) {
            CP_WAIT1();
            __syncthreads();
            const float* buf = (const float*)(dsm + ((t & 1) ? OFF_BUF1 : OFF_BUF0));
            int rows = AA - t * TT; if (rows > TT) rows = TT;
            if (tid < rows) {
                int row = t * TT + tid;
                const float* x = buf + tid * CC;     // stride 21: conflict-free
                float mx = x[0];
#pragma unroll
                for (int c = 1; c < CC; c++) mx = fmaxf(mx, x[c]);
                float s = 0.f;
#pragma unroll
                for (int c = 0; c < CC; c++) s += __expf(x[c] - mx);
                int cls = s_obj[row];
                float ce = mx + __logf(s) - x[cls];
                if (cls != 0) { cpos += ce; s_val[row] = 0.f; }
                else          s_val[row] = ce;
            }
            __syncthreads();
            int tn = t + 2;
            if (tn < NT) {
                int rows2 = AA - tn * TT; if (rows2 > TT) rows2 = TT;
                int n4 = (rows2 * CC) >> 2;
                const float4* src = sc4 + (size_t)tn * TILE_F4;
                unsigned int dbase = (unsigned int)__cvta_generic_to_shared(
                    dsm + ((tn & 1) ? OFF_BUF1 : OFF_BUF0));
#pragma unroll
                for (int j = 0; j < 6; j++) {
                    int i = tid + j * TT;
                    int ok = i < n4;
                    cp16_pred(ok ? (dbase + i * 16) : dbase,
                              ok ? (const void*)(src + i) : (const void*)sc4, ok);
                }
            }
            CP_COMMIT();
        }
        for (int off = 16; off; off >>= 1)
            cpos += __shfl_xor_sync(0xffffffffu, cpos, off);
        if (lane == 0) s_redf[wid] = cpos;
        __syncthreads();
        if (tid == 0) {
            float P = 0.f;
            for (int w2 = 0; w2 < NW; w2++) P += s_redf[w2];
            s_cpos = P;
        }
        __syncthreads();
    }

    // ---- phase D: top-k sum via 2-level histogram radix select ----
    {
        unsigned k = (unsigned)(3 * s_npos); if (k > AA) k = AA;
        unsigned* hist = (unsigned*)(dsm + OFF_BUF0);   // reuse tile buffer

        // pass 1: 2048 bins on bits [31:20)
        for (int i = tid; i < 2048; i += TT) hist[i] = 0u;
        __syncthreads();
        for (int i = tid; i < AA; i += TT)
            atomicAdd(&hist[__float_as_uint(s_val[i]) >> 20], 1u);
        __syncthreads();
        {
            int base = tid * 4;
            unsigned h0 = hist[base], h1 = hist[base + 1], h2 = hist[base + 2], h3 = hist[base + 3];
            unsigned loc = h0 + h1 + h2 + h3;
            unsigned inc = loc;
            for (int off = 1; off < 32; off <<= 1) {
                unsigned o = __shfl_down_sync(0xffffffffu, inc, off);
                if (lane < 32 - off) inc += o;
            }
            if (lane == 0) s_cnt[0][wid] = inc;
            __syncthreads();
            if (tid == 0) {
                unsigned c = 0;
                for (int w = NW - 1; w >= 0; --w) { s_cnt[1][w] = c; c += s_cnt[0][w]; }
            }
            __syncthreads();
            unsigned suf = s_cnt[1][wid] + (inc - loc);   // count in bins above my 4
            if (suf < k && suf + loc >= k) {
                unsigned c = suf;
                if      (c + h3 >= k) { s_bin1 = base + 3; s_chi = c; }
                else if (c + h3 + h2 >= k) { s_bin1 = base + 2; s_chi = c + h3; }
                else if (c + h3 + h2 + h1 >= k) { s_bin1 = base + 1; s_chi = c + h3 + h2; }
                else { s_bin1 = base; s_chi = c + h3 + h2 + h1; }
            }
        }
        __syncthreads();
        unsigned bin1 = (unsigned)s_bin1, chi = s_chi, k2 = k - chi;

        // pass 2: 4096 bins on bits [20:8) among values with top bits == bin1
        for (int i = tid; i < 4096; i += TT) hist[i] = 0u;
        __syncthreads();
        for (int i = tid; i < AA; i += TT) {
            unsigned u = __float_as_uint(s_val[i]);
            if ((u >> 20) == bin1) atomicAdd(&hist[(u >> 8) & 0xFFFu], 1u);
        }
        __syncthreads();
        {
            int base = tid * 8;
            unsigned h[8]; unsigned loc = 0;
#pragma unroll
            for (int j = 0; j < 8; j++) { h[j] = hist[base + j]; loc += h[j]; }
            unsigned inc = loc;
            for (int off = 1; off < 32; off <<= 1) {
                unsigned o = __shfl_down_sync(0xffffffffu, inc, off);
                if (lane < 32 - off) inc += o;
            }
            if (lane == 0) s_cnt[0][wid] = inc;
            __syncthreads();
            if (tid == 0) {
                unsigned c = 0;
                for (int w = NW - 1; w >= 0; --w) { s_cnt[1][w] = c; c += s_cnt[0][w]; }
            }
            __syncthreads();
            unsigned suf = s_cnt[1][wid] + (inc - loc);
            if (suf < k2 && suf + loc >= k2) {
                unsigned c = suf; int bin2 = base;
#pragma unroll
                for (int j = 7; j >= 0; --j) {
                    if (c + h[j] >= k2) { bin2 = base + j; break; }
                    c += h[j];
                }
                s_prefix = (bin1 << 20) | ((unsigned)bin2 << 8);
            }
        }
        __syncthreads();
        unsigned prefix = s_prefix;
        float kth = __uint_as_float(prefix);

        int cgt = 0; float sgt = 0.f;
        for (int i = tid; i < AA; i += TT) {
            float v = s_val[i];
            if (__float_as_uint(v) > prefix) { cgt++; sgt += v; }
        }
        for (int off = 16; off; off >>= 1) {
            cgt += __shfl_xor_sync(0xffffffffu, cgt, off);
            sgt += __shfl_xor_sync(0xffffffffu, sgt, off);
        }
        __syncthreads();
        if (lane == 0) { s_redi[wid] = cgt; s_redf[wid] = sgt; }
        __syncthreads();
        if (tid == 0) {
            int Cg = 0; float S = 0.f;
            for (int w2 = 0; w2 < NW; w2++) { Cg += s_redi[w2]; S += s_redf[w2]; }
            S += (float)((int)k - Cg) * kth;
            g_hard[b] = S;
            g_pos[b]  = s_cpos;
            g_loc[b]  = s_lsum;
            g_np[b]   = s_npos;
        }
    }

    // ---- phase E: last CTA reduces all per-image partials ----
    __threadfence();
    if (tid == 0) s_ticket = atomicAdd(&g_ctr, 1);
    __syncthreads();
    if (s_ticket == BB - 1) {
        __threadfence();
        if (tid == 0) g_ctr = 0;           // self-reset for next graph replay
        float p = 0.f, h = 0.f, l = 0.f; int n = 0;
        if (tid < BB) { p = g_pos[tid]; h = g_hard[tid]; l = g_loc[tid]; n = g_np[tid]; }
        for (int off = 16; off; off >>= 1) {
            p += __shfl_xor_sync(0xffffffffu, p, off);
            h += __shfl_xor_sync(0xffffffffu, h, off);
            l += __shfl_xor_sync(0xffffffffu, l, off);
            n += __shfl_xor_sync(0xffffffffu, n, off);
        }
        if (lane == 0) { s_redf[wid] = p + h; s_wv[0][wid] = l; s_redi[wid] = n; }
        __syncthreads();
        if (tid == 0) {
            float PH = 0.f, L = 0.f; int N = 0;
            for (int w = 0; w < NW; w++) { PH += s_redf[w]; L += s_wv[0][w]; N += s_redi[w]; }
            float np = (float)N;
            out[0] = PH / np + L / (np * 4.f);
        }
    }
}

extern "C" void kernel_launch(void* const* d_in, const int* in_sizes, int n_in,
                              void* d_out, int out_size) {
    const float* locs    = (const float*)d_in[0];
    const float* scores  = (const float*)d_in[1];
    const float* boxes   = (const float*)d_in[2];
    const int*   labels  = (const int*)d_in[3];
    const float* anchors = (const float*)d_in[4];
    float* out = (float*)d_out;

    cudaFuncSetAttribute(k_fused, cudaFuncAttributeMaxDynamicSharedMemorySize, SMEM_TOTAL);
    k_fused<<<BB, TT, SMEM_TOTAL>>>(locs, scores, boxes, labels, anchors, out);
}